// round 2
// baseline (speedup 1.0000x reference)
#include <cuda_runtime.h>
#include <cstdint>

#define NG   1024
#define DIM  128
#define HID  512
#define NREP 16

// ---- scratch (no allocations allowed) ----
__device__ float    d_escratch[NREP * NG * DIM];   // 8 MB replicated edge sums
__device__ unsigned d_ecnt[NREP * NG];             // replicated edge counts
__device__ float    d_node_mean[NG * DIM];         // per-graph node mean
__device__ int      d_idx64;                       // 1 if indices are int64

// ---------------------------------------------------------------------------
// Kernel A: detect index dtype. Node ids < 2^31, so if int64 every odd
// 32-bit word is zero. If int32, odd words are random node ids.
// ---------------------------------------------------------------------------
__global__ void detect_kernel(const void* __restrict__ edge_index) {
    const int* w = (const int*)edge_index;
    int all_zero = 1;
    #pragma unroll
    for (int i = 1; i < 128; i += 2) all_zero &= (w[i] == 0);
    d_idx64 = all_zero;
}

__device__ __forceinline__ int load_idx(const void* p, long long i, int idx64) {
    return idx64 ? (int)((const long long*)p)[i] : ((const int*)p)[i];
}

// ---------------------------------------------------------------------------
// Kernel 0: zero the edge accumulators
// ---------------------------------------------------------------------------
__global__ void zero_kernel() {
    int i = blockIdx.x * blockDim.x + threadIdx.x;
    const int nf4 = NREP * NG * DIM / 4;   // 524288 float4
    if (i < nf4) ((float4*)d_escratch)[i] = make_float4(0.f, 0.f, 0.f, 0.f);
    if (i < NREP * NG) d_ecnt[i] = 0u;
}

// ---------------------------------------------------------------------------
// Kernel 1: edge scatter-accumulate.  One warp per edge row (128 floats).
// ---------------------------------------------------------------------------
__global__ void edge_kernel(const float* __restrict__ edge_attr,
                            const void* __restrict__ edge_index,  // row 0 = src
                            const void* __restrict__ batch,
                            int n_edges) {
    int idx64  = d_idx64;
    int lane   = threadIdx.x & 31;
    int warp_g = (blockIdx.x * blockDim.x + threadIdx.x) >> 5;
    int nwarps = (gridDim.x * blockDim.x) >> 5;
    int rep    = warp_g & (NREP - 1);

    for (int e = warp_g; e < n_edges; e += nwarps) {
        int g = 0;
        if (lane == 0) {
            int src = load_idx(edge_index, e, idx64);   // first row of edge_index
            g = load_idx(batch, src, idx64);
        }
        g = __shfl_sync(0xffffffffu, g, 0);

        float4 v = ((const float4*)(edge_attr + (size_t)e * DIM))[lane];
        float* dst = d_escratch + ((size_t)rep * NG + g) * DIM + lane * 4;
        asm volatile("red.global.add.v4.f32 [%0], {%1,%2,%3,%4};"
                     :: "l"(dst), "f"(v.x), "f"(v.y), "f"(v.z), "f"(v.w)
                     : "memory");
        if (lane == 0) atomicAdd(&d_ecnt[rep * NG + g], 1u);
    }
}

// ---------------------------------------------------------------------------
// Kernel 2: node mean. batch is sorted -> contiguous segment per graph.
// One block per graph: binary search range, coalesced float4 reduction.
// ---------------------------------------------------------------------------
__global__ void node_kernel(const float* __restrict__ x,
                            const void* __restrict__ batch,
                            int n_nodes) {
    int idx64 = d_idx64;
    int g = blockIdx.x;

    // lower_bound(batch, g) and lower_bound(batch, g+1)
    int lo = 0, hi = n_nodes;
    while (lo < hi) { int m = (lo + hi) >> 1; if (load_idx(batch, m, idx64) < g) lo = m + 1; else hi = m; }
    int start = lo;
    lo = start; hi = n_nodes;
    while (lo < hi) { int m = (lo + hi) >> 1; if (load_idx(batch, m, idx64) < g + 1) lo = m + 1; else hi = m; }
    int end = lo;
    int cnt = end - start;

    int qd = threadIdx.x & 31;   // which float4 of the 128-dim row
    int r  = threadIdx.x >> 5;   // 0..7 row group

    float4 acc = make_float4(0.f, 0.f, 0.f, 0.f);
    for (int n = start + r; n < end; n += 8) {
        float4 v = ((const float4*)(x + (size_t)n * DIM))[qd];
        acc.x += v.x; acc.y += v.y; acc.z += v.z; acc.w += v.w;
    }
    __shared__ float4 sacc[8][32];
    sacc[r][qd] = acc;
    __syncthreads();
    if (r == 0) {
        float4 t = sacc[0][qd];
        #pragma unroll
        for (int i = 1; i < 8; i++) {
            float4 s = sacc[i][qd];
            t.x += s.x; t.y += s.y; t.z += s.z; t.w += s.w;
        }
        float inv = 1.0f / (float)(cnt > 0 ? cnt : 1);
        t.x *= inv; t.y *= inv; t.z *= inv; t.w *= inv;
        ((float4*)(d_node_mean + (size_t)g * DIM))[qd] = t;
    }
}

// ---------------------------------------------------------------------------
// Kernel 3: fused replica-reduce + MLP + residual + LayerNorm.
// 128 blocks x 8 graphs, 256 threads.
// ---------------------------------------------------------------------------
__global__ void __launch_bounds__(256) mlp_kernel(
        const float* __restrict__ u,
        const float* __restrict__ W1, const float* __restrict__ b1,
        const float* __restrict__ W2, const float* __restrict__ b2,
        const float* __restrict__ gamma, const float* __restrict__ beta,
        float* __restrict__ out) {
    __shared__ float inp[8][3 * DIM];   // [u | edge_mean | node_mean]
    __shared__ float hbuf[8][HID];
    __shared__ float ysm[8][DIM];
    __shared__ float ecnt_s[8];

    int tid = threadIdx.x;
    int g0  = blockIdx.x * 8;

    if (tid < 8) {
        unsigned c = 0;
        #pragma unroll
        for (int r = 0; r < NREP; r++) c += d_ecnt[r * NG + g0 + tid];
        ecnt_s[tid] = (float)(c > 0u ? c : 1u);
    }
    __syncthreads();

    // build input rows
    for (int idx = tid; idx < 8 * DIM; idx += 256) {
        int g = idx >> 7, d = idx & (DIM - 1);
        int gg = g0 + g;
        float es = 0.f;
        #pragma unroll
        for (int r = 0; r < NREP; r++)
            es += d_escratch[((size_t)r * NG + gg) * DIM + d];
        inp[g][d]           = u[(size_t)gg * DIM + d];
        inp[g][DIM + d]     = es / ecnt_s[g];
        inp[g][2 * DIM + d] = d_node_mean[(size_t)gg * DIM + d];
    }
    __syncthreads();

    // ---- layer 1: h = relu(inp @ W1 + b1), W1: [384, 512] row-major ----
    {
        float acc0[8], acc1[8];
        float bb0 = b1[tid], bb1 = b1[tid + 256];
        #pragma unroll
        for (int g = 0; g < 8; g++) { acc0[g] = bb0; acc1[g] = bb1; }

        for (int k = 0; k < 3 * DIM; k += 4) {
            float4 iv[8];
            #pragma unroll
            for (int g = 0; g < 8; g++) iv[g] = *(const float4*)&inp[g][k];
            #pragma unroll
            for (int kk = 0; kk < 4; kk++) {
                float w0 = W1[(size_t)(k + kk) * HID + tid];
                float w1 = W1[(size_t)(k + kk) * HID + tid + 256];
                #pragma unroll
                for (int g = 0; g < 8; g++) {
                    float xv = (kk == 0) ? iv[g].x : (kk == 1) ? iv[g].y
                             : (kk == 2) ? iv[g].z : iv[g].w;
                    acc0[g] = fmaf(xv, w0, acc0[g]);
                    acc1[g] = fmaf(xv, w1, acc1[g]);
                }
            }
        }
        #pragma unroll
        for (int g = 0; g < 8; g++) {
            hbuf[g][tid]       = fmaxf(acc0[g], 0.f);
            hbuf[g][tid + 256] = fmaxf(acc1[g], 0.f);
        }
    }
    __syncthreads();

    // ---- layer 2: y = h @ W2 + b2, W2: [512, 128] row-major ----
    {
        int g  = tid >> 5;
        int d0 = (tid & 31) * 4;
        float4 acc = *(const float4*)&b2[d0];
        for (int k = 0; k < HID; k++) {
            float hv = hbuf[g][k];
            float4 w = *(const float4*)&W2[(size_t)k * DIM + d0];
            acc.x = fmaf(hv, w.x, acc.x);
            acc.y = fmaf(hv, w.y, acc.y);
            acc.z = fmaf(hv, w.z, acc.z);
            acc.w = fmaf(hv, w.w, acc.w);
        }
        *(float4*)&ysm[g][d0] = acc;
    }
    __syncthreads();

    // ---- residual + layernorm: warp w handles graph w ----
    {
        int w = tid >> 5, lane = tid & 31;
        int gg = g0 + w;
        float4 v  = *(const float4*)&ysm[w][lane * 4];
        float4 uu = *(const float4*)&u[(size_t)gg * DIM + lane * 4];
        v.x += uu.x; v.y += uu.y; v.z += uu.z; v.w += uu.w;

        float s = v.x + v.y + v.z + v.w;
        #pragma unroll
        for (int off = 16; off; off >>= 1) s += __shfl_xor_sync(0xffffffffu, s, off);
        float mu = s * (1.0f / DIM);

        float dx = v.x - mu, dy = v.y - mu, dz = v.z - mu, dw = v.w - mu;
        float sq = dx * dx + dy * dy + dz * dz + dw * dw;
        #pragma unroll
        for (int off = 16; off; off >>= 1) sq += __shfl_xor_sync(0xffffffffu, sq, off);
        float rs = rsqrtf(sq * (1.0f / DIM) + 1e-5f);

        float4 gm = *(const float4*)&gamma[lane * 4];
        float4 bt = *(const float4*)&beta[lane * 4];
        float4 o;
        o.x = dx * rs * gm.x + bt.x;
        o.y = dy * rs * gm.y + bt.y;
        o.z = dz * rs * gm.z + bt.z;
        o.w = dw * rs * gm.w + bt.w;
        *(float4*)&out[(size_t)gg * DIM + lane * 4] = o;
    }
}

// ---------------------------------------------------------------------------
extern "C" void kernel_launch(void* const* d_in, const int* in_sizes, int n_in,
                              void* d_out, int out_size) {
    const float* x         = (const float*)d_in[0];
    const float* edge_attr = (const float*)d_in[1];
    const float* u         = (const float*)d_in[2];
    const float* W1        = (const float*)d_in[3];
    const float* b1        = (const float*)d_in[4];
    const float* W2        = (const float*)d_in[5];
    const float* b2        = (const float*)d_in[6];
    const float* gamma     = (const float*)d_in[7];
    const float* beta      = (const float*)d_in[8];
    const void* edge_index = d_in[9];
    const void* batch      = d_in[10];

    int n_edges = in_sizes[9] / 2;
    int n_nodes = in_sizes[10];
    float* out = (float*)d_out;

    detect_kernel<<<1, 1>>>(edge_index);
    zero_kernel<<<2048, 256>>>();
    edge_kernel<<<1184, 256>>>(edge_attr, edge_index, batch, n_edges);
    node_kernel<<<NG, 256>>>(x, batch, n_nodes);
    mlp_kernel<<<NG / 8, 256>>>(u, W1, b1, W2, b2, gamma, beta, out);
}